// round 3
// baseline (speedup 1.0000x reference)
#include <cuda_runtime.h>
#include <cuda_bf16.h>

// AttenConv fused kernel, round 2: packed fp32x2 FMA (FFMA2) version.
//
// out[u,:] = ((softmax_i( adj[u,i] ? <user[u],item[i]> : 0 )) @ item_emb) @ W
// Masked entries are 0 (not -inf) -> p = adj ? exp(s) : 1, single pass,
// no max-shift needed (scores N(0,64), exp stays in fp32 range).
//
// FFMA2 layout: accumulators paired along the user-row dimension.
//   A pairs (a[r], a[r+1]) come free as halves of LDS.128 quads.
//   B needs (b, b): V tiles are stored DUPLICATED in smem (Vt2/Vn2),
//   so (b,b) pairs are also free halves of LDS.128 quads. No pack MOVs.

#define U_DIM   8192
#define I_DIM   16384
#define D_DIM   64
#define OUT_DIM 64
#define BM      64
#define BN      64
#define NTILES  (I_DIM / BN)
#define S64     68           // stride for scalar 64-wide rows (16B aligned)
#define S128    132          // stride for duplicated 128-wide rows (16B aligned)

typedef unsigned long long ull;

__device__ __forceinline__ ull fma2(ull a, ull b, ull c) {
    ull d;
    asm("fma.rn.f32x2 %0, %1, %2, %3;" : "=l"(d) : "l"(a), "l"(b), "l"(c));
    return d;
}
__device__ __forceinline__ ull pk(float lo, float hi) {
    ull d;
    asm("mov.b64 %0, {%1, %2};" : "=l"(d) : "f"(lo), "f"(hi));
    return d;
}
__device__ __forceinline__ void upk(ull v, float& lo, float& hi) {
    asm("mov.b64 {%0, %1}, %2;" : "=f"(lo), "=f"(hi) : "l"(v));
}

__global__ void __launch_bounds__(256, 1)
atten_conv_kernel(const float* __restrict__ user_emb,
                  const float* __restrict__ item_emb,
                  const float* __restrict__ Wmat,
                  const int*   __restrict__ adj,
                  float*       __restrict__ out)
{
    extern __shared__ float sm[];
    float* Ut    = sm;                    // [64][S64]   U transposed: Ut[d][u]
    float* Ws    = Ut  + 64 * S64;        // [64][S64]   W natural:    Ws[d][o]
    float* Pt    = Ws  + 64 * S64;        // [64][S64]   P transposed: Pt[i][u] (reused as At[d][u])
    float* Vt2   = Pt  + 64 * S64;        // [64][S128]  V transposed DUP: Vt2[d][2i..2i+1]
    float* Vn2   = Vt2 + 64 * S128;       // [64][S128]  V natural    DUP: Vn2[i][2d..2d+1]
    float* den_s = Vn2 + 64 * S128;       // [64]

    const int tid = threadIdx.x;
    const int tx  = tid & 15;             // item/out-col group
    const int ty  = tid >> 4;             // user-row group
    const int u0  = blockIdx.x * BM;

    // ---- prologue: U transposed (scalar) + W natural into smem ----
    {
        const int row = tid >> 2;         // 0..63
        const int d0  = (tid & 3) * 16;
        const float4* up = (const float4*)(user_emb + (u0 + row) * D_DIM + d0);
        #pragma unroll
        for (int j = 0; j < 4; j++) {
            float4 v = up[j];
            int d = d0 + 4 * j;
            Ut[(d + 0) * S64 + row] = v.x;
            Ut[(d + 1) * S64 + row] = v.y;
            Ut[(d + 2) * S64 + row] = v.z;
            Ut[(d + 3) * S64 + row] = v.w;
        }
        const float4* wp = (const float4*)(Wmat + row * OUT_DIM + d0);
        #pragma unroll
        for (int j = 0; j < 4; j++)
            *(float4*)(Ws + row * S64 + d0 + 4 * j) = wp[j];
    }

    // GEMM2 accumulator: num2[h][c] = (num[2h][4tx+c], num[2h+1][4tx+c])
    ull   num2[2][4] = {};
    float den_r[4]   = {0.f, 0.f, 0.f, 0.f};

    // ---- preload V tile 0 ----
    const int vrow = tid >> 2;            // item within tile (0..63)
    const int vd0  = (tid & 3) * 16;      // d-chunk start
    float4 vreg[4];
    {
        const float4* vp = (const float4*)(item_emb + vrow * D_DIM + vd0);
        #pragma unroll
        for (int j = 0; j < 4; j++) vreg[j] = vp[j];
    }

    for (int t = 0; t < NTILES; t++) {
        const int i0 = t * BN;

        __syncthreads();                  // prev GEMM2 done with Vn2/Pt
        // stage V tile, duplicated, both majors
        #pragma unroll
        for (int j = 0; j < 4; j++) {
            const float4 v = vreg[j];
            const int d = vd0 + 4 * j;
            // Vn2[item][2d..]: pairs (v,v) contiguous in d
            *(float4*)(Vn2 + vrow * S128 + 2 * d)     = make_float4(v.x, v.x, v.y, v.y);
            *(float4*)(Vn2 + vrow * S128 + 2 * d + 4) = make_float4(v.z, v.z, v.w, v.w);
            // Vt2[d][2*item], [2*item+1]
            *(float2*)(Vt2 + (d + 0) * S128 + 2 * vrow) = make_float2(v.x, v.x);
            *(float2*)(Vt2 + (d + 1) * S128 + 2 * vrow) = make_float2(v.y, v.y);
            *(float2*)(Vt2 + (d + 2) * S128 + 2 * vrow) = make_float2(v.z, v.z);
            *(float2*)(Vt2 + (d + 3) * S128 + 2 * vrow) = make_float2(v.w, v.w);
        }
        __syncthreads();

        // prefetch next V tile (hidden behind GEMM1)
        {
            int tn = (t + 1 < NTILES) ? (t + 1) : t;
            const float4* vp = (const float4*)(item_emb + (tn * BN + vrow) * D_DIM + vd0);
            #pragma unroll
            for (int j = 0; j < 4; j++) vreg[j] = vp[j];
        }
        // adj for this thread's 4x4 patch
        int4 areg[4];
        #pragma unroll
        for (int r = 0; r < 4; r++)
            areg[r] = *(const int4*)(adj + (u0 + 4 * ty + r) * I_DIM + i0 + 4 * tx);

        // ---- GEMM1: s2[h][c] = (S[2h][c], S[2h+1][c]) over k=0..63 ----
        ull s2[2][4] = {};
        #pragma unroll 8
        for (int k = 0; k < D_DIM; k++) {
            const float4 af = *(const float4*)(Ut + k * S64 + 4 * ty);
            const ull a01 = pk(af.x, af.y);
            const ull a23 = pk(af.z, af.w);
            const float4 b0 = *(const float4*)(Vt2 + k * S128 + 8 * tx);
            const float4 b1 = *(const float4*)(Vt2 + k * S128 + 8 * tx + 4);
            const ull bd[4] = { pk(b0.x, b0.y), pk(b0.z, b0.w),
                                pk(b1.x, b1.y), pk(b1.z, b1.w) };
            #pragma unroll
            for (int c = 0; c < 4; c++) {
                s2[0][c] = fma2(a01, bd[c], s2[0][c]);
                s2[1][c] = fma2(a23, bd[c], s2[1][c]);
            }
        }

        // ---- mask + exp + den, store P transposed (scalar) ----
        float p[4][4];
        #pragma unroll
        for (int h = 0; h < 2; h++) {
            #pragma unroll
            for (int c = 0; c < 4; c++) {
                float slo, shi;
                upk(s2[h][c], slo, shi);
                const int* a0 = (const int*)&areg[2 * h];
                const int* a1 = (const int*)&areg[2 * h + 1];
                float e0 = __expf(slo), e1 = __expf(shi);
                float p0 = (a0[c] > 0) ? e0 : 1.0f;
                float p1 = (a1[c] > 0) ? e1 : 1.0f;
                p[2 * h][c]     = p0;  den_r[2 * h]     += p0;
                p[2 * h + 1][c] = p1;  den_r[2 * h + 1] += p1;
            }
        }
        #pragma unroll
        for (int c = 0; c < 4; c++)
            *(float4*)(Pt + (4 * tx + c) * S64 + 4 * ty) =
                make_float4(p[0][c], p[1][c], p[2][c], p[3][c]);
        __syncthreads();

        // ---- GEMM2: num2 += P @ V  (k = item within tile) ----
        #pragma unroll 8
        for (int k = 0; k < BN; k++) {
            const float4 af = *(const float4*)(Pt + k * S64 + 4 * ty);
            const ull a01 = pk(af.x, af.y);
            const ull a23 = pk(af.z, af.w);
            const float4 b0 = *(const float4*)(Vn2 + k * S128 + 8 * tx);
            const float4 b1 = *(const float4*)(Vn2 + k * S128 + 8 * tx + 4);
            const ull bd[4] = { pk(b0.x, b0.y), pk(b0.z, b0.w),
                                pk(b1.x, b1.y), pk(b1.z, b1.w) };
            #pragma unroll
            for (int c = 0; c < 4; c++) {
                num2[0][c] = fma2(a01, bd[c], num2[0][c]);
                num2[1][c] = fma2(a23, bd[c], num2[1][c]);
            }
        }
    }

    // ---- unpack num, reduce den across the 16 tx lanes ----
    float num[4][4];
    #pragma unroll
    for (int h = 0; h < 2; h++)
        #pragma unroll
        for (int c = 0; c < 4; c++)
            upk(num2[h][c], num[2 * h][c], num[2 * h + 1][c]);

    #pragma unroll
    for (int r = 0; r < 4; r++) {
        float d = den_r[r];
        #pragma unroll
        for (int off = 8; off >= 1; off >>= 1)
            d += __shfl_xor_sync(0xffffffffu, d, off);
        if (tx == 0) den_s[4 * ty + r] = d;
    }
    __syncthreads();

    float dinv[4];
    #pragma unroll
    for (int r = 0; r < 4; r++) dinv[r] = 1.0f / den_s[4 * ty + r];

    // store A = num/den transposed into Pt (At[d][u])
    #pragma unroll
    for (int c = 0; c < 4; c++)
        *(float4*)(Pt + (4 * tx + c) * S64 + 4 * ty) =
            make_float4(num[0][c] * dinv[0], num[1][c] * dinv[1],
                        num[2][c] * dinv[2], num[3][c] * dinv[3]);
    __syncthreads();

    // ---- GEMM3: out = A @ W (tiny, scalar) ----
    float o[4][4] = {};
    #pragma unroll 16
    for (int k = 0; k < D_DIM; k++) {
        const float4 af = *(const float4*)(Pt + k * S64 + 4 * ty);
        const float4 bf = *(const float4*)(Ws + k * S64 + 4 * tx);
        const float av[4] = {af.x, af.y, af.z, af.w};
        const float bv[4] = {bf.x, bf.y, bf.z, bf.w};
        #pragma unroll
        for (int r = 0; r < 4; r++)
            #pragma unroll
            for (int c = 0; c < 4; c++)
                o[r][c] = fmaf(av[r], bv[c], o[r][c]);
    }

    #pragma unroll
    for (int r = 0; r < 4; r++)
        *(float4*)(out + (u0 + 4 * ty + r) * OUT_DIM + 4 * tx) =
            make_float4(o[r][0], o[r][1], o[r][2], o[r][3]);
}

extern "C" void kernel_launch(void* const* d_in, const int* in_sizes, int n_in,
                              void* d_out, int out_size)
{
    const float* user_emb = (const float*)d_in[0];
    const float* item_emb = (const float*)d_in[1];
    const float* Wmat     = (const float*)d_in[2];
    const int*   adj      = (const int*)d_in[3];
    float*       out      = (float*)d_out;

    const int smem_bytes = (3 * 64 * S64 + 2 * 64 * S128 + 64) * (int)sizeof(float); // 120064
    cudaFuncSetAttribute(atten_conv_kernel,
                         cudaFuncAttributeMaxDynamicSharedMemorySize, smem_bytes);
    atten_conv_kernel<<<U_DIM / BM, 256, smem_bytes>>>(user_emb, item_emb, Wmat, adj, out);
}

// round 5
// speedup vs baseline: 5.1990x; 5.1990x over previous
#include <cuda_runtime.h>
#include <cuda_bf16.h>
#include <cstdint>

// AttenConv round 4: warp-level mma.sync (HMMA) bf16x3-split flash kernel.
// out[u,:] = softmax_i(adj?<U_u,V_i>:0) @ V @ W ;  p = adj ? exp(s) : 1.
// fp32 emulated as bf16 hi/lo: x*y ~= xh*yh + xh*yl + xl*yh (3 MMAs).
// P stays entirely in registers (GEMM1 C-frag == GEMM2 A-frag layout).

#define U_DIM   8192
#define I_DIM   16384
#define D_DIM   64
#define OUT_DIM 64
#define BM      64          // users per CTA
#define BN      128         // items per tile
#define NT      (I_DIM / BN)
#define VSTR    144         // bytes per 64-bf16 row (72 halves; conflict-free ldmatrix)

// smem byte offsets (all 128B aligned)
#define SM_WS   0                       // W fp32 [64][64]          16384
#define SM_NUM  16384                   // num fp32 [64][68]        17408
#define SM_DEN  33792                   // den fp32 [64]            256
#define SM_UHI  34048                   // U hi bf16 [64][72]       9216
#define SM_ULO  43264                   // U lo bf16 [64][72]       9216
#define SM_V    52480                   // V bufs [2][hi/lo][128][72]  73728
#define VBUFSZ  18432
#define SMEM_TOTAL 126208

__device__ __forceinline__ uint32_t smem_u32(const void* p) {
    uint32_t a;
    asm("{ .reg .u64 t; cvta.to.shared.u64 t, %1; cvt.u32.u64 %0, t; }" : "=r"(a) : "l"(p));
    return a;
}
__device__ __forceinline__ void mma16816(float& d0, float& d1, float& d2, float& d3,
                                         uint32_t a0, uint32_t a1, uint32_t a2, uint32_t a3,
                                         uint32_t b0, uint32_t b1) {
    asm volatile("mma.sync.aligned.m16n8k16.row.col.f32.bf16.bf16.f32 "
                 "{%0,%1,%2,%3},{%4,%5,%6,%7},{%8,%9},{%0,%1,%2,%3};"
                 : "+f"(d0), "+f"(d1), "+f"(d2), "+f"(d3)
                 : "r"(a0), "r"(a1), "r"(a2), "r"(a3), "r"(b0), "r"(b1));
}
__device__ __forceinline__ void ldsm4(uint32_t& r0, uint32_t& r1, uint32_t& r2, uint32_t& r3,
                                      uint32_t addr) {
    asm volatile("ldmatrix.sync.aligned.m8n8.x4.shared.b16 {%0,%1,%2,%3}, [%4];"
                 : "=r"(r0), "=r"(r1), "=r"(r2), "=r"(r3) : "r"(addr));
}
__device__ __forceinline__ void ldsm4t(uint32_t& r0, uint32_t& r1, uint32_t& r2, uint32_t& r3,
                                       uint32_t addr) {
    asm volatile("ldmatrix.sync.aligned.m8n8.x4.trans.shared.b16 {%0,%1,%2,%3}, [%4];"
                 : "=r"(r0), "=r"(r1), "=r"(r2), "=r"(r3) : "r"(addr));
}
// pack (lo elem = x0, hi elem = x1) into bf16x2
__device__ __forceinline__ uint32_t cvt2(float x0, float x1) {
    uint32_t r;
    asm("cvt.rn.bf16x2.f32 %0, %1, %2;" : "=r"(r) : "f"(x1), "f"(x0));
    return r;
}
// hi/lo bf16 split of a pair
__device__ __forceinline__ void split2(float x0, float x1, uint32_t& h, uint32_t& l) {
    h = cvt2(x0, x1);
    float h0 = __uint_as_float(h << 16);
    float h1 = __uint_as_float(h & 0xFFFF0000u);
    l = cvt2(x0 - h0, x1 - h1);
}

__global__ void __launch_bounds__(256, 1)
atten_hmma_kernel(const float* __restrict__ user_emb,
                  const float* __restrict__ item_emb,
                  const float* __restrict__ Wmat,
                  const int*   __restrict__ adj,
                  float*       __restrict__ out)
{
    extern __shared__ __align__(128) char smc[];
    const uint32_t sb = smem_u32(smc);
    const int tid = threadIdx.x;
    const int w   = tid >> 5;
    const int l   = tid & 31;
    const int m   = w & 3;          // user m-group (rows 16m..16m+15)
    const int h   = w >> 2;         // item half (64h..64h+63 within tile)
    const int u0  = blockIdx.x * BM;

    // ---- prologue: stage W, U(hi/lo), V tile 0 ----
    {   // W fp32 -> smem
        const float4* wp = (const float4*)Wmat;
        float4* ws = (float4*)(smc + SM_WS);
        #pragma unroll
        for (int j = 0; j < 4; j++) ws[tid + 256 * j] = wp[tid + 256 * j];
    }
    if (tid < 128) {   // U: row = tid>>1, d-half = (tid&1)*32
        const int row = tid >> 1, d0 = (tid & 1) * 32;
        const float4* up = (const float4*)(user_emb + (long)(u0 + row) * D_DIM + d0);
        #pragma unroll
        for (int j = 0; j < 8; j++) {
            float4 v = up[j];
            uint32_t h0, l0, h1, l1;
            split2(v.x, v.y, h0, l0);
            split2(v.z, v.w, h1, l1);
            const int off = row * VSTR + (d0 + 4 * j) * 2;
            *(uint2*)(smc + SM_UHI + off) = make_uint2(h0, h1);
            *(uint2*)(smc + SM_ULO + off) = make_uint2(l0, l1);
        }
    }
    {   // V tile 0 -> buf 0
        const int row = tid >> 1, d0 = (tid & 1) * 32;
        const float4* vp = (const float4*)(item_emb + (long)row * D_DIM + d0);
        #pragma unroll
        for (int j = 0; j < 8; j++) {
            float4 v = vp[j];
            uint32_t h0, l0, h1, l1;
            split2(v.x, v.y, h0, l0);
            split2(v.z, v.w, h1, l1);
            const int off = row * VSTR + (d0 + 4 * j) * 2;
            *(uint2*)(smc + SM_V + off)          = make_uint2(h0, h1);
            *(uint2*)(smc + SM_V + VBUFSZ + off) = make_uint2(l0, l1);
        }
    }
    __syncthreads();

    // ---- persistent U A-fragments ----
    uint32_t auh[4][4], aul[4][4];
    {
        const uint32_t abase = (16 * m + (l & 15)) * VSTR + (l >> 4) * 16;
        #pragma unroll
        for (int kk = 0; kk < 4; kk++) {
            ldsm4(auh[kk][0], auh[kk][1], auh[kk][2], auh[kk][3], sb + SM_UHI + abase + kk * 32);
            ldsm4(aul[kk][0], aul[kk][1], aul[kk][2], aul[kk][3], sb + SM_ULO + abase + kk * 32);
        }
    }

    // per-lane ldmatrix base offsets (bytes within a V split buffer)
    const uint32_t g1base = (64 * h + (l & 7) + (l >> 4) * 8) * VSTR + (((l >> 3) & 1) * 8) * 2;
    const uint32_t g2base = (64 * h + (l & 7) + ((l >> 3) & 1) * 8) * VSTR + ((l >> 4) * 8) * 2;

    float num[8][4] = {};
    float den0 = 0.f, den1 = 0.f;

    const long adjr0 = (long)(u0 + 16 * m + (l >> 2)) * I_DIM + 64 * h + 2 * (l & 3);
    const long adjr1 = adjr0 + 8L * I_DIM;

    // V staging geometry for this thread
    const int vrow = tid >> 1, vd0 = (tid & 1) * 32;

    #pragma unroll 1
    for (int t = 0; t < NT; t++) {
        const uint32_t vhi = sb + SM_V + (t & 1) * 2 * VBUFSZ;
        const uint32_t vlo = vhi + VBUFSZ;

        // prefetch next V tile (fp32) and this tile's adj
        float4 vreg[8];
        {
            const long tn = (t + 1 < NT) ? (t + 1) : t;
            const float4* vp = (const float4*)(item_emb + (tn * BN + vrow) * (long)D_DIM + vd0);
            #pragma unroll
            for (int j = 0; j < 8; j++) vreg[j] = vp[j];
        }
        int2 a0r[8], a1r[8];
        {
            const int2* p0 = (const int2*)(adj + adjr0 + (long)t * BN);
            const int2* p1 = (const int2*)(adj + adjr1 + (long)t * BN);
            #pragma unroll
            for (int nt = 0; nt < 8; nt++) { a0r[nt] = p0[4 * nt]; a1r[nt] = p1[4 * nt]; }
        }

        // ---- GEMM1: S[16 x 64] = U x V^T (3-term bf16 split) ----
        float s[8][4] = {};
        #pragma unroll
        for (int kk = 0; kk < 4; kk++) {
            #pragma unroll
            for (int jn = 0; jn < 4; jn++) {
                const uint32_t off = jn * (16 * VSTR) + kk * 32;
                uint32_t bh0, bh1, bh2, bh3, bl0, bl1, bl2, bl3;
                ldsm4(bh0, bh1, bh2, bh3, vhi + g1base + off);
                ldsm4(bl0, bl1, bl2, bl3, vlo + g1base + off);
                float* s0 = s[2 * jn];
                float* s1 = s[2 * jn + 1];
                mma16816(s0[0], s0[1], s0[2], s0[3], auh[kk][0], auh[kk][1], auh[kk][2], auh[kk][3], bh0, bh1);
                mma16816(s0[0], s0[1], s0[2], s0[3], auh[kk][0], auh[kk][1], auh[kk][2], auh[kk][3], bl0, bl1);
                mma16816(s0[0], s0[1], s0[2], s0[3], aul[kk][0], aul[kk][1], aul[kk][2], aul[kk][3], bh0, bh1);
                mma16816(s1[0], s1[1], s1[2], s1[3], auh[kk][0], auh[kk][1], auh[kk][2], auh[kk][3], bh2, bh3);
                mma16816(s1[0], s1[1], s1[2], s1[3], auh[kk][0], auh[kk][1], auh[kk][2], auh[kk][3], bl2, bl3);
                mma16816(s1[0], s1[1], s1[2], s1[3], aul[kk][0], aul[kk][1], aul[kk][2], aul[kk][3], bh2, bh3);
            }
        }

        // ---- epilogue in registers: p = adj ? exp(s) : 1 ; bf16 split ----
        uint32_t phA[8], phB[8], plA[8], plB[8];
        #pragma unroll
        for (int nt = 0; nt < 8; nt++) {
            float p00 = (a0r[nt].x > 0) ? __expf(s[nt][0]) : 1.0f;
            float p01 = (a0r[nt].y > 0) ? __expf(s[nt][1]) : 1.0f;
            float p10 = (a1r[nt].x > 0) ? __expf(s[nt][2]) : 1.0f;
            float p11 = (a1r[nt].y > 0) ? __expf(s[nt][3]) : 1.0f;
            den0 += p00 + p01;
            den1 += p10 + p11;
            split2(p00, p01, phA[nt], plA[nt]);
            split2(p10, p11, phB[nt], plB[nt]);
        }

        // ---- GEMM2: num[16 x 64] += P x V (3-term) ----
        #pragma unroll
        for (int kk = 0; kk < 4; kk++) {
            const uint32_t ah0 = phA[2 * kk], ah1 = phB[2 * kk], ah2 = phA[2 * kk + 1], ah3 = phB[2 * kk + 1];
            const uint32_t al0 = plA[2 * kk], al1 = plB[2 * kk], al2 = plA[2 * kk + 1], al3 = plB[2 * kk + 1];
            #pragma unroll
            for (int jd = 0; jd < 4; jd++) {
                const uint32_t off = kk * (16 * VSTR) + jd * 32;
                uint32_t bh0, bh1, bh2, bh3, bl0, bl1, bl2, bl3;
                ldsm4t(bh0, bh1, bh2, bh3, vhi + g2base + off);
                ldsm4t(bl0, bl1, bl2, bl3, vlo + g2base + off);
                float* n0 = num[2 * jd];
                float* n1 = num[2 * jd + 1];
                mma16816(n0[0], n0[1], n0[2], n0[3], ah0, ah1, ah2, ah3, bh0, bh1);
                mma16816(n0[0], n0[1], n0[2], n0[3], ah0, ah1, ah2, ah3, bl0, bl1);
                mma16816(n0[0], n0[1], n0[2], n0[3], al0, al1, al2, al3, bh0, bh1);
                mma16816(n1[0], n1[1], n1[2], n1[3], ah0, ah1, ah2, ah3, bh2, bh3);
                mma16816(n1[0], n1[1], n1[2], n1[3], ah0, ah1, ah2, ah3, bl2, bl3);
                mma16816(n1[0], n1[1], n1[2], n1[3], al0, al1, al2, al3, bh2, bh3);
            }
        }

        // ---- stage next V tile into the other buffer ----
        {
            char* dsthi = smc + SM_V + ((t + 1) & 1) * 2 * VBUFSZ;
            char* dstlo = dsthi + VBUFSZ;
            #pragma unroll
            for (int j = 0; j < 8; j++) {
                uint32_t h0, l0, h1, l1;
                split2(vreg[j].x, vreg[j].y, h0, l0);
                split2(vreg[j].z, vreg[j].w, h1, l1);
                const int off = vrow * VSTR + (vd0 + 4 * j) * 2;
                *(uint2*)(dsthi + off) = make_uint2(h0, h1);
                *(uint2*)(dstlo + off) = make_uint2(l0, l1);
            }
        }
        __syncthreads();
    }

    // ---- combine num partials across the two item halves ----
    float* numb = (float*)(smc + SM_NUM);
    const int r0 = 16 * m + (l >> 2), r1 = r0 + 8;
    const int cb = 2 * (l & 3);
    if (h == 0) {
        #pragma unroll
        for (int nt = 0; nt < 8; nt++) {
            *(float2*)(numb + r0 * 68 + 8 * nt + cb) = make_float2(num[nt][0], num[nt][1]);
            *(float2*)(numb + r1 * 68 + 8 * nt + cb) = make_float2(num[nt][2], num[nt][3]);
        }
    }
    __syncthreads();
    if (h == 1) {
        #pragma unroll
        for (int nt = 0; nt < 8; nt++) {
            float2* q0 = (float2*)(numb + r0 * 68 + 8 * nt + cb);
            float2* q1 = (float2*)(numb + r1 * 68 + 8 * nt + cb);
            float2 v0 = *q0, v1 = *q1;
            *q0 = make_float2(v0.x + num[nt][0], v0.y + num[nt][1]);
            *q1 = make_float2(v1.x + num[nt][2], v1.y + num[nt][3]);
        }
    }

    // ---- den: lane-reduce then combine halves ----
    float* dens = (float*)(smc + SM_DEN);
    den0 += __shfl_xor_sync(0xffffffffu, den0, 1);
    den0 += __shfl_xor_sync(0xffffffffu, den0, 2);
    den1 += __shfl_xor_sync(0xffffffffu, den1, 1);
    den1 += __shfl_xor_sync(0xffffffffu, den1, 2);
    __syncthreads();
    if (h == 0 && (l & 3) == 0) { dens[r0] = den0; dens[r1] = den1; }
    __syncthreads();
    if (h == 1 && (l & 3) == 0) { dens[r0] += den0; dens[r1] += den1; }
    __syncthreads();

    // ---- GEMM3: out = (num/den) @ W ----
    {
        const int r  = tid >> 2;
        const int c0 = (tid & 3) * 16;
        const float dinv = 1.0f / dens[r];
        const float* ws = (const float*)(smc + SM_WS);
        float acc[16] = {};
        #pragma unroll 8
        for (int k = 0; k < 64; k++) {
            const float a = numb[r * 68 + k];
            const float4* wr = (const float4*)(ws + k * 64 + c0);
            #pragma unroll
            for (int q = 0; q < 4; q++) {
                float4 wv = wr[q];
                acc[4 * q + 0] = fmaf(a, wv.x, acc[4 * q + 0]);
                acc[4 * q + 1] = fmaf(a, wv.y, acc[4 * q + 1]);
                acc[4 * q + 2] = fmaf(a, wv.z, acc[4 * q + 2]);
                acc[4 * q + 3] = fmaf(a, wv.w, acc[4 * q + 3]);
            }
        }
        float4* op = (float4*)(out + (long)(u0 + r) * OUT_DIM + c0);
        #pragma unroll
        for (int q = 0; q < 4; q++)
            op[q] = make_float4(acc[4 * q] * dinv, acc[4 * q + 1] * dinv,
                                acc[4 * q + 2] * dinv, acc[4 * q + 3] * dinv);
    }
}

extern "C" void kernel_launch(void* const* d_in, const int* in_sizes, int n_in,
                              void* d_out, int out_size)
{
    const float* user_emb = (const float*)d_in[0];
    const float* item_emb = (const float*)d_in[1];
    const float* Wmat     = (const float*)d_in[2];
    const int*   adj      = (const int*)d_in[3];
    float*       out      = (float*)d_out;

    cudaFuncSetAttribute(atten_hmma_kernel,
                         cudaFuncAttributeMaxDynamicSharedMemorySize, SMEM_TOTAL);
    atten_hmma_kernel<<<U_DIM / BM, 256, SMEM_TOTAL>>>(user_emb, item_emb, Wmat, adj, out);
}

// round 6
// speedup vs baseline: 7.4050x; 1.4243x over previous
#include <cuda_runtime.h>
#include <cuda_bf16.h>
#include <cstdint>

// AttenConv round 5: HMMA bf16x3 flash kernel, 512 threads, cp.async V staging.
// out[u,:] = softmax_i(adj?<U_u,V_i>:0) @ V @ W ;  p = adj ? exp(s) : 1.
// V is pre-split into bf16 hi/lo planes (padded rows) by a tiny precompute
// kernel; the main loop cp.async's tiles (no per-tile split ALU, no regs).

#define U_DIM   8192
#define I_DIM   16384
#define D_DIM   64
#define OUT_DIM 64
#define BM      64          // users per CTA
#define BN      128         // items per tile
#define NT      (I_DIM / BN)
#define VSTR    144         // bytes per 64-bf16 row (72 halves, conflict-free ldsm)
#define ROWB    18432       // 128 rows * 144B = one tile plane
#define VBUFSZ  36864       // hi + lo planes

// smem byte offsets
#define SM_U_HI 0           // U hi bf16 [64][72]   9216
#define SM_U_LO 9216        // U lo bf16 [64][72]   9216   (aliased by W at end)
#define SM_DEN  18432       // dens[4][64] fp32     1024
#define SM_V    19456       // V bufs [2][hi|lo]    73728  (aliased by num[4][64][68] at end)
#define SMEM_TOTAL 93184

__device__ __align__(16) __nv_bfloat16 g_vhi[I_DIM][72];
__device__ __align__(16) __nv_bfloat16 g_vlo[I_DIM][72];

__device__ __forceinline__ uint32_t smem_u32(const void* p) {
    uint32_t a;
    asm("{ .reg .u64 t; cvta.to.shared.u64 t, %1; cvt.u32.u64 %0, t; }" : "=r"(a) : "l"(p));
    return a;
}
__device__ __forceinline__ void cp16(uint32_t dst, const void* src) {
    asm volatile("cp.async.cg.shared.global [%0], [%1], 16;" :: "r"(dst), "l"(src));
}
#define CP_COMMIT() asm volatile("cp.async.commit_group;" ::: "memory")
#define CP_WAIT1()  asm volatile("cp.async.wait_group 1;" ::: "memory")

__device__ __forceinline__ void mma16816(float& d0, float& d1, float& d2, float& d3,
                                         uint32_t a0, uint32_t a1, uint32_t a2, uint32_t a3,
                                         uint32_t b0, uint32_t b1) {
    asm volatile("mma.sync.aligned.m16n8k16.row.col.f32.bf16.bf16.f32 "
                 "{%0,%1,%2,%3},{%4,%5,%6,%7},{%8,%9},{%0,%1,%2,%3};"
                 : "+f"(d0), "+f"(d1), "+f"(d2), "+f"(d3)
                 : "r"(a0), "r"(a1), "r"(a2), "r"(a3), "r"(b0), "r"(b1));
}
__device__ __forceinline__ void ldsm4(uint32_t& r0, uint32_t& r1, uint32_t& r2, uint32_t& r3,
                                      uint32_t addr) {
    asm volatile("ldmatrix.sync.aligned.m8n8.x4.shared.b16 {%0,%1,%2,%3}, [%4];"
                 : "=r"(r0), "=r"(r1), "=r"(r2), "=r"(r3) : "r"(addr));
}
__device__ __forceinline__ void ldsm4t(uint32_t& r0, uint32_t& r1, uint32_t& r2, uint32_t& r3,
                                       uint32_t addr) {
    asm volatile("ldmatrix.sync.aligned.m8n8.x4.trans.shared.b16 {%0,%1,%2,%3}, [%4];"
                 : "=r"(r0), "=r"(r1), "=r"(r2), "=r"(r3) : "r"(addr));
}
__device__ __forceinline__ uint32_t cvt2(float x0, float x1) {
    uint32_t r;
    asm("cvt.rn.bf16x2.f32 %0, %1, %2;" : "=r"(r) : "f"(x1), "f"(x0));
    return r;
}
__device__ __forceinline__ void split2(float x0, float x1, uint32_t& h, uint32_t& l) {
    h = cvt2(x0, x1);
    float h0 = __uint_as_float(h << 16);
    float h1 = __uint_as_float(h & 0xFFFF0000u);
    l = cvt2(x0 - h0, x1 - h1);
}

// ---- precompute: split item_emb into bf16 hi/lo planes with VSTR padding ----
__global__ void __launch_bounds__(256)
vsplit_kernel(const float* __restrict__ item_emb)
{
    const int gid  = blockIdx.x * 256 + threadIdx.x;   // 131072 threads
    const int item = gid >> 3;
    const int d0   = (gid & 7) * 8;
    const float4* vp = (const float4*)(item_emb + (long)item * D_DIM + d0);
    const float4 v0 = vp[0], v1 = vp[1];
    uint32_t h0, l0, h1, l1, h2, l2, h3, l3;
    split2(v0.x, v0.y, h0, l0); split2(v0.z, v0.w, h1, l1);
    split2(v1.x, v1.y, h2, l2); split2(v1.z, v1.w, h3, l3);
    *(uint4*)&g_vhi[item][d0] = make_uint4(h0, h1, h2, h3);
    *(uint4*)&g_vlo[item][d0] = make_uint4(l0, l1, l2, l3);
}

__global__ void __launch_bounds__(512, 1)
atten_hmma_kernel(const float* __restrict__ user_emb,
                  const float* __restrict__ item_emb,
                  const float* __restrict__ Wmat,
                  const int*   __restrict__ adj,
                  float*       __restrict__ out)
{
    extern __shared__ __align__(128) char smc[];
    const uint32_t sb = smem_u32(smc);
    const int tid = threadIdx.x;
    const int w   = tid >> 5;
    const int l   = tid & 31;
    const int m   = w & 3;          // user group: rows 16m..16m+15
    const int q   = w >> 2;         // item quarter: items 32q..32q+31 in tile
    const int u0  = blockIdx.x * BM;

    const char* vhib = (const char*)g_vhi;
    const char* vlob = (const char*)g_vlo;

    // ---- prologue: stage U hi/lo; cp.async V tile 0 into buf 0 ----
    {
        const int row = tid >> 3, d0 = (tid & 7) * 8;
        const float4* up = (const float4*)(user_emb + (long)(u0 + row) * D_DIM + d0);
        const float4 v0 = up[0], v1 = up[1];
        uint32_t h0, l0h, h1, l1h, h2, l2h, h3, l3h;
        split2(v0.x, v0.y, h0, l0h); split2(v0.z, v0.w, h1, l1h);
        split2(v1.x, v1.y, h2, l2h); split2(v1.z, v1.w, h3, l3h);
        *(uint4*)(smc + SM_U_HI + row * VSTR + d0 * 2) = make_uint4(h0, h1, h2, h3);
        *(uint4*)(smc + SM_U_LO + row * VSTR + d0 * 2) = make_uint4(l0h, l1h, l2h, l3h);
    }
    for (int idx = tid; idx < 1152; idx += 512) {
        cp16(sb + SM_V + idx * 16,         vhib + idx * 16);
        cp16(sb + SM_V + ROWB + idx * 16,  vlob + idx * 16);
    }
    CP_COMMIT();
    __syncthreads();

    // ---- persistent U A-fragments ----
    uint32_t auh[4][4], aul[4][4];
    {
        const uint32_t abase = (16 * m + (l & 15)) * VSTR + (l >> 4) * 16;
        #pragma unroll
        for (int kk = 0; kk < 4; kk++) {
            ldsm4(auh[kk][0], auh[kk][1], auh[kk][2], auh[kk][3], sb + SM_U_HI + abase + kk * 32);
            ldsm4(aul[kk][0], aul[kk][1], aul[kk][2], aul[kk][3], sb + SM_U_LO + abase + kk * 32);
        }
    }

    // ldmatrix lane bases within a V plane (quarter q)
    const uint32_t g1base = (32 * q + (l & 7) + (l >> 4) * 8) * VSTR + (((l >> 3) & 1) * 8) * 2;
    const uint32_t g2base = (32 * q + (l & 7) + ((l >> 3) & 1) * 8) * VSTR + (l >> 4) * 16;

    float num[8][4] = {};
    float den0 = 0.f, den1 = 0.f;

    const int r0 = 16 * m + (l >> 2), r1 = r0 + 8;
    const int cb = 2 * (l & 3);
    const long adjr0 = (long)(u0 + r0) * I_DIM + 32 * q + cb;
    const long adjr1 = adjr0 + 8L * I_DIM;

    #pragma unroll 1
    for (int t = 0; t < NT; t++) {
        // stage tile t+1 (no-op at t = NT-1; empty commit keeps group count)
        if (t + 1 < NT) {
            const long srcoff = (long)(t + 1) * ROWB;
            const uint32_t db = sb + SM_V + ((t + 1) & 1) * VBUFSZ;
            for (int idx = tid; idx < 1152; idx += 512) {
                cp16(db + idx * 16,        vhib + srcoff + idx * 16);
                cp16(db + ROWB + idx * 16, vlob + srcoff + idx * 16);
            }
        }
        CP_COMMIT();

        // adj for this tile (LDG, overlaps the wait below)
        int2 a0r[4], a1r[4];
        {
            const int2* p0 = (const int2*)(adj + adjr0 + (long)t * BN);
            const int2* p1 = (const int2*)(adj + adjr1 + (long)t * BN);
            #pragma unroll
            for (int nt = 0; nt < 4; nt++) { a0r[nt] = p0[4 * nt]; a1r[nt] = p1[4 * nt]; }
        }

        CP_WAIT1();
        __syncthreads();                 // buf t ready for everyone

        const uint32_t vhi = sb + SM_V + (t & 1) * VBUFSZ;
        const uint32_t vlo = vhi + ROWB;

        // ---- GEMM1: S[16 x 32] = U x V^T (3-term) ----
        float s[4][4] = {};
        #pragma unroll
        for (int kk = 0; kk < 4; kk++) {
            #pragma unroll
            for (int jn = 0; jn < 2; jn++) {
                const uint32_t off = jn * (16 * VSTR) + kk * 32;
                uint32_t bh0, bh1, bh2, bh3, bl0, bl1, bl2, bl3;
                ldsm4(bh0, bh1, bh2, bh3, vhi + g1base + off);
                ldsm4(bl0, bl1, bl2, bl3, vlo + g1base + off);
                float* s0 = s[2 * jn];
                float* s1 = s[2 * jn + 1];
                mma16816(s0[0], s0[1], s0[2], s0[3], auh[kk][0], auh[kk][1], auh[kk][2], auh[kk][3], bh0, bh1);
                mma16816(s0[0], s0[1], s0[2], s0[3], auh[kk][0], auh[kk][1], auh[kk][2], auh[kk][3], bl0, bl1);
                mma16816(s0[0], s0[1], s0[2], s0[3], aul[kk][0], aul[kk][1], aul[kk][2], aul[kk][3], bh0, bh1);
                mma16816(s1[0], s1[1], s1[2], s1[3], auh[kk][0], auh[kk][1], auh[kk][2], auh[kk][3], bh2, bh3);
                mma16816(s1[0], s1[1], s1[2], s1[3], auh[kk][0], auh[kk][1], auh[kk][2], auh[kk][3], bl2, bl3);
                mma16816(s1[0], s1[1], s1[2], s1[3], aul[kk][0], aul[kk][1], aul[kk][2], aul[kk][3], bh2, bh3);
            }
        }

        // ---- epilogue: p = adj ? exp(s) : 1, bf16 split (registers only) ----
        uint32_t phA[4], phB[4], plA[4], plB[4];
        #pragma unroll
        for (int nt = 0; nt < 4; nt++) {
            float p00 = (a0r[nt].x > 0) ? __expf(s[nt][0]) : 1.0f;
            float p01 = (a0r[nt].y > 0) ? __expf(s[nt][1]) : 1.0f;
            float p10 = (a1r[nt].x > 0) ? __expf(s[nt][2]) : 1.0f;
            float p11 = (a1r[nt].y > 0) ? __expf(s[nt][3]) : 1.0f;
            den0 += p00 + p01;
            den1 += p10 + p11;
            split2(p00, p01, phA[nt], plA[nt]);
            split2(p10, p11, phB[nt], plB[nt]);
        }

        // ---- GEMM2: num[16 x 64] += P x V (3-term) ----
        #pragma unroll
        for (int kk = 0; kk < 2; kk++) {
            const uint32_t ah0 = phA[2 * kk], ah1 = phB[2 * kk], ah2 = phA[2 * kk + 1], ah3 = phB[2 * kk + 1];
            const uint32_t al0 = plA[2 * kk], al1 = plB[2 * kk], al2 = plA[2 * kk + 1], al3 = plB[2 * kk + 1];
            #pragma unroll
            for (int jd = 0; jd < 4; jd++) {
                const uint32_t off = kk * (16 * VSTR) + jd * 32;
                uint32_t bh0, bh1, bh2, bh3, bl0, bl1, bl2, bl3;
                ldsm4t(bh0, bh1, bh2, bh3, vhi + g2base + off);
                ldsm4t(bl0, bl1, bl2, bl3, vlo + g2base + off);
                float* n0 = num[2 * jd];
                float* n1 = num[2 * jd + 1];
                mma16816(n0[0], n0[1], n0[2], n0[3], ah0, ah1, ah2, ah3, bh0, bh1);
                mma16816(n0[0], n0[1], n0[2], n0[3], ah0, ah1, ah2, ah3, bl0, bl1);
                mma16816(n0[0], n0[1], n0[2], n0[3], al0, al1, al2, al3, bh0, bh1);
                mma16816(n1[0], n1[1], n1[2], n1[3], ah0, ah1, ah2, ah3, bh2, bh3);
                mma16816(n1[0], n1[1], n1[2], n1[3], ah0, ah1, ah2, ah3, bl2, bl3);
                mma16816(n1[0], n1[1], n1[2], n1[3], al0, al1, al2, al3, bh2, bh3);
            }
        }
        __syncthreads();                 // protect buf being rewritten next iter
    }

    // ---- end phase: reduce num/den across item quarters, then GEMM3 ----
    float* numq = (float*)(smc + SM_V);          // [4][64][68] fp32 (aliases V)
    float* dens = (float*)(smc + SM_DEN);        // [4][64]

    #pragma unroll
    for (int nd = 0; nd < 8; nd++) {
        *(float2*)(numq + q * (64 * 68) + r0 * 68 + 8 * nd + cb) = make_float2(num[nd][0], num[nd][1]);
        *(float2*)(numq + q * (64 * 68) + r1 * 68 + 8 * nd + cb) = make_float2(num[nd][2], num[nd][3]);
    }
    den0 += __shfl_xor_sync(0xffffffffu, den0, 1);
    den0 += __shfl_xor_sync(0xffffffffu, den0, 2);
    den1 += __shfl_xor_sync(0xffffffffu, den1, 1);
    den1 += __shfl_xor_sync(0xffffffffu, den1, 2);
    if ((l & 3) == 0) { dens[q * 64 + r0] = den0; dens[q * 64 + r1] = den1; }
    __syncthreads();

    // reduce num across q into q=0 slab; stage W into U region (dead now)
    {
        const int row = tid >> 3, c0 = (tid & 7) * 8;
        float acc[8];
        #pragma unroll
        for (int j = 0; j < 8; j++) acc[j] = numq[row * 68 + c0 + j];
        #pragma unroll
        for (int qq = 1; qq < 4; qq++)
            #pragma unroll
            for (int j = 0; j < 8; j++)
                acc[j] += numq[qq * (64 * 68) + row * 68 + c0 + j];
        #pragma unroll
        for (int j = 0; j < 8; j++) numq[row * 68 + c0 + j] = acc[j];

        const float4* wp = (const float4*)Wmat;
        float4* ws = (float4*)(smc + SM_U_HI);
        ws[tid]       = wp[tid];
        ws[tid + 512] = wp[tid + 512];
    }
    __syncthreads();

    // GEMM3: out = (num/den) @ W
    {
        const int row = tid >> 3, c0 = (tid & 7) * 8;
        const float dinv = 1.0f / (dens[row] + dens[64 + row] + dens[128 + row] + dens[192 + row]);
        const float* ws = (const float*)(smc + SM_U_HI);
        float acc[8] = {};
        #pragma unroll 8
        for (int k = 0; k < 64; k++) {
            const float a = numq[row * 68 + k];
            const float4 w0 = *(const float4*)(ws + k * 64 + c0);
            const float4 w1 = *(const float4*)(ws + k * 64 + c0 + 4);
            acc[0] = fmaf(a, w0.x, acc[0]); acc[1] = fmaf(a, w0.y, acc[1]);
            acc[2] = fmaf(a, w0.z, acc[2]); acc[3] = fmaf(a, w0.w, acc[3]);
            acc[4] = fmaf(a, w1.x, acc[4]); acc[5] = fmaf(a, w1.y, acc[5]);
            acc[6] = fmaf(a, w1.z, acc[6]); acc[7] = fmaf(a, w1.w, acc[7]);
        }
        float4* op = (float4*)(out + (long)(u0 + row) * OUT_DIM + c0);
        op[0] = make_float4(acc[0] * dinv, acc[1] * dinv, acc[2] * dinv, acc[3] * dinv);
        op[1] = make_float4(acc[4] * dinv, acc[5] * dinv, acc[6] * dinv, acc[7] * dinv);
    }
}

extern "C" void kernel_launch(void* const* d_in, const int* in_sizes, int n_in,
                              void* d_out, int out_size)
{
    const float* user_emb = (const float*)d_in[0];
    const float* item_emb = (const float*)d_in[1];
    const float* Wmat     = (const float*)d_in[2];
    const int*   adj      = (const int*)d_in[3];
    float*       out      = (float*)d_out;

    vsplit_kernel<<<I_DIM * D_DIM / 8 / 256, 256>>>(item_emb);
    cudaFuncSetAttribute(atten_hmma_kernel,
                         cudaFuncAttributeMaxDynamicSharedMemorySize, SMEM_TOTAL);
    atten_hmma_kernel<<<U_DIM / BM, 512, SMEM_TOTAL>>>(user_emb, item_emb, Wmat, adj, out);
}

// round 7
// speedup vs baseline: 7.7777x; 1.0503x over previous
#include <cuda_runtime.h>
#include <cuda_bf16.h>
#include <cstdint>

// AttenConv round 6: HMMA bf16x3 flash kernel, 256 threads x 2 CTAs/SM.
// out[u,:] = softmax_i(adj?<U_u,V_i>:0) @ V @ W ;  p = adj ? exp(s) : 1.
// V pre-split into bf16 hi/lo planes once; main loop cp.async's tiles.
// Round 6 change: BM 64->32, 2 co-resident CTAs per SM to hide barrier /
// pipeline latency that bound round 5 (occ 25%, tensor 45%).

#define U_DIM   8192
#define I_DIM   16384
#define D_DIM   64
#define OUT_DIM 64
#define BM      32          // users per CTA
#define BN      128         // items per tile
#define NT      (I_DIM / BN)
#define VSTR    144         // bytes per 64-bf16 row (72 halves, conflict-free ldsm)
#define ROWB    18432       // 128 rows * 144B = one tile plane
#define VBUFSZ  36864       // hi + lo planes

// smem byte offsets
#define SM_U_HI 0           // U hi bf16 [32][72]   4608
#define SM_U_LO 4608        // U lo bf16 [32][72]   4608
#define SM_DEN  9216        // dens[4][32] fp32     512
#define SM_V    9728        // V bufs [2][hi|lo]    73728
#define SM_NUMA SM_V                 // end-phase alias: num [4][32][68] fp32 = 34816
#define SM_WA   (SM_V + 34816)       // end-phase alias: W fp32 [64][64] = 16384
#define SMEM_TOTAL 83456

__device__ __align__(16) __nv_bfloat16 g_vhi[I_DIM][72];
__device__ __align__(16) __nv_bfloat16 g_vlo[I_DIM][72];

__device__ __forceinline__ uint32_t smem_u32(const void* p) {
    uint32_t a;
    asm("{ .reg .u64 t; cvta.to.shared.u64 t, %1; cvt.u32.u64 %0, t; }" : "=r"(a) : "l"(p));
    return a;
}
__device__ __forceinline__ void cp16(uint32_t dst, const void* src) {
    asm volatile("cp.async.cg.shared.global [%0], [%1], 16;" :: "r"(dst), "l"(src));
}
#define CP_COMMIT() asm volatile("cp.async.commit_group;" ::: "memory")
#define CP_WAIT1()  asm volatile("cp.async.wait_group 1;" ::: "memory")

__device__ __forceinline__ void mma16816(float& d0, float& d1, float& d2, float& d3,
                                         uint32_t a0, uint32_t a1, uint32_t a2, uint32_t a3,
                                         uint32_t b0, uint32_t b1) {
    asm volatile("mma.sync.aligned.m16n8k16.row.col.f32.bf16.bf16.f32 "
                 "{%0,%1,%2,%3},{%4,%5,%6,%7},{%8,%9},{%0,%1,%2,%3};"
                 : "+f"(d0), "+f"(d1), "+f"(d2), "+f"(d3)
                 : "r"(a0), "r"(a1), "r"(a2), "r"(a3), "r"(b0), "r"(b1));
}
__device__ __forceinline__ void ldsm4(uint32_t& r0, uint32_t& r1, uint32_t& r2, uint32_t& r3,
                                      uint32_t addr) {
    asm volatile("ldmatrix.sync.aligned.m8n8.x4.shared.b16 {%0,%1,%2,%3}, [%4];"
                 : "=r"(r0), "=r"(r1), "=r"(r2), "=r"(r3) : "r"(addr));
}
__device__ __forceinline__ void ldsm4t(uint32_t& r0, uint32_t& r1, uint32_t& r2, uint32_t& r3,
                                       uint32_t addr) {
    asm volatile("ldmatrix.sync.aligned.m8n8.x4.trans.shared.b16 {%0,%1,%2,%3}, [%4];"
                 : "=r"(r0), "=r"(r1), "=r"(r2), "=r"(r3) : "r"(addr));
}
__device__ __forceinline__ uint32_t cvt2(float x0, float x1) {
    uint32_t r;
    asm("cvt.rn.bf16x2.f32 %0, %1, %2;" : "=r"(r) : "f"(x1), "f"(x0));
    return r;
}
__device__ __forceinline__ void split2(float x0, float x1, uint32_t& h, uint32_t& l) {
    h = cvt2(x0, x1);
    float h0 = __uint_as_float(h << 16);
    float h1 = __uint_as_float(h & 0xFFFF0000u);
    l = cvt2(x0 - h0, x1 - h1);
}

// ---- precompute: split item_emb into bf16 hi/lo planes with VSTR padding ----
__global__ void __launch_bounds__(256)
vsplit_kernel(const float* __restrict__ item_emb)
{
    const int gid  = blockIdx.x * 256 + threadIdx.x;
    const int item = gid >> 3;
    const int d0   = (gid & 7) * 8;
    const float4* vp = (const float4*)(item_emb + (long)item * D_DIM + d0);
    const float4 v0 = vp[0], v1 = vp[1];
    uint32_t h0, l0, h1, l1, h2, l2, h3, l3;
    split2(v0.x, v0.y, h0, l0); split2(v0.z, v0.w, h1, l1);
    split2(v1.x, v1.y, h2, l2); split2(v1.z, v1.w, h3, l3);
    *(uint4*)&g_vhi[item][d0] = make_uint4(h0, h1, h2, h3);
    *(uint4*)&g_vlo[item][d0] = make_uint4(l0, l1, l2, l3);
}

__global__ void __launch_bounds__(256, 2)
atten_hmma_kernel(const float* __restrict__ user_emb,
                  const float* __restrict__ item_emb,
                  const float* __restrict__ Wmat,
                  const int*   __restrict__ adj,
                  float*       __restrict__ out)
{
    extern __shared__ __align__(128) char smc[];
    const uint32_t sb = smem_u32(smc);
    const int tid = threadIdx.x;
    const int w   = tid >> 5;
    const int l   = tid & 31;
    const int m   = w & 1;          // user group: rows 16m..16m+15
    const int q   = w >> 1;         // item quarter: items 32q..32q+31 in tile
    const int u0  = blockIdx.x * BM;

    const char* vhib = (const char*)g_vhi;
    const char* vlob = (const char*)g_vlo;

    // ---- prologue: stage U hi/lo; cp.async V tile 0 into buf 0 ----
    if (tid < 256) {
        const int row = tid >> 3, d0 = (tid & 7) * 8;
        if (row < BM) {
            const float4* up = (const float4*)(user_emb + (long)(u0 + row) * D_DIM + d0);
            const float4 v0 = up[0], v1 = up[1];
            uint32_t h0, l0h, h1, l1h, h2, l2h, h3, l3h;
            split2(v0.x, v0.y, h0, l0h); split2(v0.z, v0.w, h1, l1h);
            split2(v1.x, v1.y, h2, l2h); split2(v1.z, v1.w, h3, l3h);
            *(uint4*)(smc + SM_U_HI + row * VSTR + d0 * 2) = make_uint4(h0, h1, h2, h3);
            *(uint4*)(smc + SM_U_LO + row * VSTR + d0 * 2) = make_uint4(l0h, l1h, l2h, l3h);
        }
    }
    for (int idx = tid; idx < 1152; idx += 256) {
        cp16(sb + SM_V + idx * 16,         vhib + idx * 16);
        cp16(sb + SM_V + ROWB + idx * 16,  vlob + idx * 16);
    }
    CP_COMMIT();
    __syncthreads();

    // ---- persistent U A-fragments ----
    uint32_t auh[4][4], aul[4][4];
    {
        const uint32_t abase = (16 * m + (l & 15)) * VSTR + (l >> 4) * 16;
        #pragma unroll
        for (int kk = 0; kk < 4; kk++) {
            ldsm4(auh[kk][0], auh[kk][1], auh[kk][2], auh[kk][3], sb + SM_U_HI + abase + kk * 32);
            ldsm4(aul[kk][0], aul[kk][1], aul[kk][2], aul[kk][3], sb + SM_U_LO + abase + kk * 32);
        }
    }

    // ldmatrix lane bases within a V plane (quarter q)
    const uint32_t g1base = (32 * q + (l & 7) + (l >> 4) * 8) * VSTR + (((l >> 3) & 1) * 8) * 2;
    const uint32_t g2base = (32 * q + (l & 7) + ((l >> 3) & 1) * 8) * VSTR + (l >> 4) * 16;

    float num[8][4] = {};
    float den0 = 0.f, den1 = 0.f;

    const int r0 = 16 * m + (l >> 2), r1 = r0 + 8;
    const int cb = 2 * (l & 3);
    const long adjr0 = (long)(u0 + r0) * I_DIM + 32 * q + cb;
    const long adjr1 = adjr0 + 8L * I_DIM;

    #pragma unroll 1
    for (int t = 0; t < NT; t++) {
        // stage tile t+1 (empty commit at the last iter keeps group count)
        if (t + 1 < NT) {
            const long srcoff = (long)(t + 1) * ROWB;
            const uint32_t db = sb + SM_V + ((t + 1) & 1) * VBUFSZ;
            for (int idx = tid; idx < 1152; idx += 256) {
                cp16(db + idx * 16,        vhib + srcoff + idx * 16);
                cp16(db + ROWB + idx * 16, vlob + srcoff + idx * 16);
            }
        }
        CP_COMMIT();

        // adj for this tile (overlaps the wait below)
        int2 a0r[4], a1r[4];
        {
            const int2* p0 = (const int2*)(adj + adjr0 + (long)t * BN);
            const int2* p1 = (const int2*)(adj + adjr1 + (long)t * BN);
            #pragma unroll
            for (int nt = 0; nt < 4; nt++) { a0r[nt] = p0[4 * nt]; a1r[nt] = p1[4 * nt]; }
        }

        CP_WAIT1();
        __syncthreads();                 // buf t ready for everyone

        const uint32_t vhi = sb + SM_V + (t & 1) * VBUFSZ;
        const uint32_t vlo = vhi + ROWB;

        // ---- GEMM1: S[16 x 32] = U x V^T (3-term) ----
        float s[4][4] = {};
        #pragma unroll
        for (int kk = 0; kk < 4; kk++) {
            #pragma unroll
            for (int jn = 0; jn < 2; jn++) {
                const uint32_t off = jn * (16 * VSTR) + kk * 32;
                uint32_t bh0, bh1, bh2, bh3, bl0, bl1, bl2, bl3;
                ldsm4(bh0, bh1, bh2, bh3, vhi + g1base + off);
                ldsm4(bl0, bl1, bl2, bl3, vlo + g1base + off);
                float* s0 = s[2 * jn];
                float* s1 = s[2 * jn + 1];
                mma16816(s0[0], s0[1], s0[2], s0[3], auh[kk][0], auh[kk][1], auh[kk][2], auh[kk][3], bh0, bh1);
                mma16816(s0[0], s0[1], s0[2], s0[3], auh[kk][0], auh[kk][1], auh[kk][2], auh[kk][3], bl0, bl1);
                mma16816(s0[0], s0[1], s0[2], s0[3], aul[kk][0], aul[kk][1], aul[kk][2], aul[kk][3], bh0, bh1);
                mma16816(s1[0], s1[1], s1[2], s1[3], auh[kk][0], auh[kk][1], auh[kk][2], auh[kk][3], bh2, bh3);
                mma16816(s1[0], s1[1], s1[2], s1[3], auh[kk][0], auh[kk][1], auh[kk][2], auh[kk][3], bl2, bl3);
                mma16816(s1[0], s1[1], s1[2], s1[3], aul[kk][0], aul[kk][1], aul[kk][2], aul[kk][3], bh2, bh3);
            }
        }

        // ---- epilogue: p = adj ? exp(s) : 1, bf16 split (registers only) ----
        uint32_t phA[4], phB[4], plA[4], plB[4];
        #pragma unroll
        for (int nt = 0; nt < 4; nt++) {
            float p00 = (a0r[nt].x > 0) ? __expf(s[nt][0]) : 1.0f;
            float p01 = (a0r[nt].y > 0) ? __expf(s[nt][1]) : 1.0f;
            float p10 = (a1r[nt].x > 0) ? __expf(s[nt][2]) : 1.0f;
            float p11 = (a1r[nt].y > 0) ? __expf(s[nt][3]) : 1.0f;
            den0 += p00 + p01;
            den1 += p10 + p11;
            split2(p00, p01, phA[nt], plA[nt]);
            split2(p10, p11, phB[nt], plB[nt]);
        }

        // ---- GEMM2: num[16 x 64] += P x V (3-term) ----
        #pragma unroll
        for (int kk = 0; kk < 2; kk++) {
            const uint32_t ah0 = phA[2 * kk], ah1 = phB[2 * kk], ah2 = phA[2 * kk + 1], ah3 = phB[2 * kk + 1];
            const uint32_t al0 = plA[2 * kk], al1 = plB[2 * kk], al2 = plA[2 * kk + 1], al3 = plB[2 * kk + 1];
            #pragma unroll
            for (int jd = 0; jd < 4; jd++) {
                const uint32_t off = kk * (16 * VSTR) + jd * 32;
                uint32_t bh0, bh1, bh2, bh3, bl0, bl1, bl2, bl3;
                ldsm4t(bh0, bh1, bh2, bh3, vhi + g2base + off);
                ldsm4t(bl0, bl1, bl2, bl3, vlo + g2base + off);
                float* n0 = num[2 * jd];
                float* n1 = num[2 * jd + 1];
                mma16816(n0[0], n0[1], n0[2], n0[3], ah0, ah1, ah2, ah3, bh0, bh1);
                mma16816(n0[0], n0[1], n0[2], n0[3], ah0, ah1, ah2, ah3, bl0, bl1);
                mma16816(n0[0], n0[1], n0[2], n0[3], al0, al1, al2, al3, bh0, bh1);
                mma16816(n1[0], n1[1], n1[2], n1[3], ah0, ah1, ah2, ah3, bh2, bh3);
                mma16816(n1[0], n1[1], n1[2], n1[3], ah0, ah1, ah2, ah3, bl2, bl3);
                mma16816(n1[0], n1[1], n1[2], n1[3], al0, al1, al2, al3, bh2, bh3);
            }
        }
        __syncthreads();                 // protect buf being rewritten next iter
    }

    // ---- end phase: reduce num/den across item quarters, then GEMM3 ----
    float* numq = (float*)(smc + SM_NUMA);       // [4][32][68] fp32 (aliases V)
    float* dens = (float*)(smc + SM_DEN);        // [4][32]

    #pragma unroll
    for (int nd = 0; nd < 8; nd++) {
        *(float2*)(numq + q * (32 * 68) + r0 * 68 + 8 * nd + cb) = make_float2(num[nd][0], num[nd][1]);
        *(float2*)(numq + q * (32 * 68) + r1 * 68 + 8 * nd + cb) = make_float2(num[nd][2], num[nd][3]);
    }
    den0 += __shfl_xor_sync(0xffffffffu, den0, 1);
    den0 += __shfl_xor_sync(0xffffffffu, den0, 2);
    den1 += __shfl_xor_sync(0xffffffffu, den1, 1);
    den1 += __shfl_xor_sync(0xffffffffu, den1, 2);
    if ((l & 3) == 0) { dens[q * 32 + r0] = den0; dens[q * 32 + r1] = den1; }
    __syncthreads();

    // reduce num across q into q=0 slab; stage W into its alias region
    {
        const int row = tid >> 3, c0 = (tid & 7) * 8;
        float acc[8];
        #pragma unroll
        for (int j = 0; j < 8; j++) acc[j] = numq[row * 68 + c0 + j];
        #pragma unroll
        for (int qq = 1; qq < 4; qq++)
            #pragma unroll
            for (int j = 0; j < 8; j++)
                acc[j] += numq[qq * (32 * 68) + row * 68 + c0 + j];
        #pragma unroll
        for (int j = 0; j < 8; j++) numq[row * 68 + c0 + j] = acc[j];

        const float4* wp = (const float4*)Wmat;
        float4* ws = (float4*)(smc + SM_WA);
        #pragma unroll
        for (int j = 0; j < 4; j++) ws[tid + 256 * j] = wp[tid + 256 * j];
    }
    __syncthreads();

    // GEMM3: out = (num/den) @ W
    {
        const int row = tid >> 3, c0 = (tid & 7) * 8;
        const float dinv = 1.0f / (dens[row] + dens[32 + row] + dens[64 + row] + dens[96 + row]);
        const float* ws = (const float*)(smc + SM_WA);
        float acc[8] = {};
        #pragma unroll 8
        for (int k = 0; k < 64; k++) {
            const float a = numq[row * 68 + k];
            const float4 w0 = *(const float4*)(ws + k * 64 + c0);
            const float4 w1 = *(const float4*)(ws + k * 64 + c0 + 4);
            acc[0] = fmaf(a, w0.x, acc[0]); acc[1] = fmaf(a, w0.y, acc[1]);
            acc[2] = fmaf(a, w0.z, acc[2]); acc[3] = fmaf(a, w0.w, acc[3]);
            acc[4] = fmaf(a, w1.x, acc[4]); acc[5] = fmaf(a, w1.y, acc[5]);
            acc[6] = fmaf(a, w1.z, acc[6]); acc[7] = fmaf(a, w1.w, acc[7]);
        }
        float4* op = (float4*)(out + (long)(u0 + row) * OUT_DIM + c0);
        op[0] = make_float4(acc[0] * dinv, acc[1] * dinv, acc[2] * dinv, acc[3] * dinv);
        op[1] = make_float4(acc[4] * dinv, acc[5] * dinv, acc[6] * dinv, acc[7] * dinv);
    }
}

extern "C" void kernel_launch(void* const* d_in, const int* in_sizes, int n_in,
                              void* d_out, int out_size)
{
    const float* user_emb = (const float*)d_in[0];
    const float* item_emb = (const float*)d_in[1];
    const float* Wmat     = (const float*)d_in[2];
    const int*   adj      = (const int*)d_in[3];
    float*       out      = (float*)d_out;

    vsplit_kernel<<<I_DIM * D_DIM / 8 / 256, 256>>>(item_emb);
    cudaFuncSetAttribute(atten_hmma_kernel,
                         cudaFuncAttributeMaxDynamicSharedMemorySize, SMEM_TOTAL);
    atten_hmma_kernel<<<U_DIM / BM, 256, SMEM_TOTAL>>>(user_emb, item_emb, Wmat, adj, out);
}